// round 1
// baseline (speedup 1.0000x reference)
#include <cuda_runtime.h>
#include <cmath>

// ---------------------------------------------------------------------------
// Problem constants
// ---------------------------------------------------------------------------
static constexpr int B_   = 4;
static constexpr int S_   = 1024;
static constexpr int D_   = 1024;
static constexpr int H_   = 16;
static constexpr int DH_  = 64;       // D/H
static constexpr int E_   = 8;
static constexpr int FF1_ = 4096;
static constexpr int FF2_ = 2048;
static constexpr int NTOK = B_ * S_;  // 4096

// ---------------------------------------------------------------------------
// Scratch (static device globals; allocation inside kernel_launch is banned)
// ---------------------------------------------------------------------------
__device__ float g_hn1  [(size_t)NTOK * D_];            //  16 MB
__device__ float g_qkv  [(size_t)NTOK * 3 * D_];        //  50 MB
__device__ float g_scores[(size_t)B_ * H_ * S_ * S_];   // 268 MB (also holds P)
__device__ float g_attno[(size_t)NTOK * D_];            //  16 MB
__device__ float g_h2   [(size_t)NTOK * D_];            //  16 MB  x + attn
__device__ float g_hn2  [(size_t)NTOK * D_];            //  16 MB
__device__ float g_gate [NTOK];
__device__ float g_h1   [(size_t)NTOK * E_ * FF1_];     // 537 MB
__device__ float g_act  [(size_t)NTOK * E_ * FF2_];     // 268 MB

// ---------------------------------------------------------------------------
// Generic tiled fp32 GEMM:  C = alpha * A(MxK) * B  (+ epilogue)
//   BT=true : B is [N,K] row-major (C[m,n] = sum_k A[m,k]*B[n,k])
//   BT=false: B is [K,N] row-major
//   Two-level batch offset: bz -> (zb = bz/zDiv, zh = bz%zDiv)
//   EPI 0: C = alpha*acc
//   EPI 1: C = alpha*acc + Res            (Res same layout/offset as C)
//   EPI 2: C = Res + acc * Gvec[row]
// ---------------------------------------------------------------------------
template<int EPI, bool BT>
__global__ void __launch_bounds__(256)
gemm_k(const float* __restrict__ A, const float* __restrict__ B,
       float* __restrict__ C, const float* __restrict__ Res,
       const float* __restrict__ Gvec,
       int M, int N, int K, int lda, int ldb, int ldc,
       int zDiv, long sA1, long sA2, long sB1, long sB2, long sC1, long sC2,
       float alpha)
{
    constexpr int BM = 128, BN = 128, BK = 16;
    __shared__ float As[BK][BM];
    __shared__ float Bs[BK][BN];

    const int bz = blockIdx.z;
    const int zb = bz / zDiv;
    const int zh = bz - zb * zDiv;
    A += (size_t)zb * sA1 + (size_t)zh * sA2;
    B += (size_t)zb * sB1 + (size_t)zh * sB2;
    const size_t coff = (size_t)zb * sC1 + (size_t)zh * sC2;
    C += coff;
    if (EPI == 1 || EPI == 2) Res += coff;

    const int bm  = blockIdx.y * BM;
    const int bn  = blockIdx.x * BN;
    const int tid = threadIdx.x;
    const int tx  = tid & 15;        // 0..15
    const int ty  = tid >> 4;        // 0..15

    // A / NT-B load mapping: 128 rows x 16 k, 8 floats per thread
    const int arow = tid >> 1;            // 0..127
    const int akc  = (tid & 1) * 8;       // 0 or 8
    // NN-B load mapping: 16 k-rows x 128 n-cols
    const int bkr  = tid >> 4;            // 0..15
    const int bnc  = (tid & 15) * 8;      // 0..120

    float acc[8][8];
    #pragma unroll
    for (int i = 0; i < 8; i++)
        #pragma unroll
        for (int j = 0; j < 8; j++) acc[i][j] = 0.f;

    for (int k0 = 0; k0 < K; k0 += BK) {
        // ---- load A tile (K is always a multiple of 16; M a multiple of 128)
        {
            const int gm = bm + arow;
            const float* ap = A + (size_t)gm * lda + k0 + akc;
            float4 v0 = *(const float4*)ap;
            float4 v1 = *(const float4*)(ap + 4);
            As[akc + 0][arow] = v0.x; As[akc + 1][arow] = v0.y;
            As[akc + 2][arow] = v0.z; As[akc + 3][arow] = v0.w;
            As[akc + 4][arow] = v1.x; As[akc + 5][arow] = v1.y;
            As[akc + 6][arow] = v1.z; As[akc + 7][arow] = v1.w;
        }
        // ---- load B tile
        if (BT) {
            const int gn = bn + arow;
            if (gn < N) {
                const float* bp = B + (size_t)gn * ldb + k0 + akc;
                float4 v0 = *(const float4*)bp;
                float4 v1 = *(const float4*)(bp + 4);
                Bs[akc + 0][arow] = v0.x; Bs[akc + 1][arow] = v0.y;
                Bs[akc + 2][arow] = v0.z; Bs[akc + 3][arow] = v0.w;
                Bs[akc + 4][arow] = v1.x; Bs[akc + 5][arow] = v1.y;
                Bs[akc + 6][arow] = v1.z; Bs[akc + 7][arow] = v1.w;
            } else {
                #pragma unroll
                for (int i = 0; i < 8; i++) Bs[akc + i][arow] = 0.f;
            }
        } else {
            const int gk = k0 + bkr;
            const int gn = bn + bnc;
            const float* bp = B + (size_t)gk * ldb + gn;
            if (gn + 7 < N) {
                *(float4*)&Bs[bkr][bnc]     = *(const float4*)bp;
                *(float4*)&Bs[bkr][bnc + 4] = *(const float4*)(bp + 4);
            } else {
                #pragma unroll
                for (int i = 0; i < 8; i++)
                    Bs[bkr][bnc + i] = (gn + i < N) ? bp[i] : 0.f;
            }
        }
        __syncthreads();

        // ---- compute
        #pragma unroll
        for (int kk = 0; kk < BK; kk++) {
            float4 a0 = *(const float4*)&As[kk][ty * 8];
            float4 a1 = *(const float4*)&As[kk][ty * 8 + 4];
            float4 b0 = *(const float4*)&Bs[kk][tx * 8];
            float4 b1 = *(const float4*)&Bs[kk][tx * 8 + 4];
            float a[8] = {a0.x, a0.y, a0.z, a0.w, a1.x, a1.y, a1.z, a1.w};
            float b[8] = {b0.x, b0.y, b0.z, b0.w, b1.x, b1.y, b1.z, b1.w};
            #pragma unroll
            for (int i = 0; i < 8; i++)
                #pragma unroll
                for (int j = 0; j < 8; j++)
                    acc[i][j] += a[i] * b[j];
        }
        __syncthreads();
    }

    // ---- epilogue
    #pragma unroll
    for (int i = 0; i < 8; i++) {
        const int gm = bm + ty * 8 + i;
        if (gm >= M) continue;
        #pragma unroll
        for (int j = 0; j < 8; j++) {
            const int gn = bn + tx * 8 + j;
            if (gn >= N) continue;
            const size_t idx = (size_t)gm * ldc + gn;
            float v;
            if (EPI == 0)      v = alpha * acc[i][j];
            else if (EPI == 1) v = alpha * acc[i][j] + Res[idx];
            else               v = Res[idx] + acc[i][j] * Gvec[gm];
            C[idx] = v;
        }
    }
}

// ---------------------------------------------------------------------------
// RMSNorm over rows of length 1024
// ---------------------------------------------------------------------------
__global__ void rmsnorm_k(const float* __restrict__ x, const float* __restrict__ w,
                          float* __restrict__ y, float eps)
{
    const int row = blockIdx.x;
    const float* xr = x + (size_t)row * D_;
    float s = 0.f;
    for (int i = threadIdx.x; i < D_; i += 256) { float v = xr[i]; s += v * v; }
    __shared__ float red[256];
    red[threadIdx.x] = s;
    __syncthreads();
    for (int off = 128; off > 0; off >>= 1) {
        if (threadIdx.x < off) red[threadIdx.x] += red[threadIdx.x + off];
        __syncthreads();
    }
    const float inv = rsqrtf(red[0] / (float)D_ + eps);
    float* yr = y + (size_t)row * D_;
    for (int i = threadIdx.x; i < D_; i += 256) yr[i] = xr[i] * inv * w[i];
}

// ---------------------------------------------------------------------------
// Row softmax over 1024-length rows (in place, for attention scores)
// ---------------------------------------------------------------------------
__global__ void softmax_k(float* __restrict__ sc)
{
    float* p = sc + (size_t)blockIdx.x * S_;
    const int t = threadIdx.x;
    __shared__ float red[256];

    float m = -INFINITY;
    for (int i = t; i < S_; i += 256) m = fmaxf(m, p[i]);
    red[t] = m; __syncthreads();
    for (int off = 128; off > 0; off >>= 1) {
        if (t < off) red[t] = fmaxf(red[t], red[t + off]);
        __syncthreads();
    }
    m = red[0];
    __syncthreads();

    float sum = 0.f;
    for (int i = t; i < S_; i += 256) {
        float e = __expf(p[i] - m);
        p[i] = e;
        sum += e;
    }
    red[t] = sum; __syncthreads();
    for (int off = 128; off > 0; off >>= 1) {
        if (t < off) red[t] += red[t + off];
        __syncthreads();
    }
    const float inv = 1.f / red[0];
    for (int i = t; i < S_; i += 256) p[i] *= inv;
}

// ---------------------------------------------------------------------------
// Gating: logits -> rmsnorm(E) -> softmax(/0.5) -> top1 -> g/(g+1e-6)
// One warp per token.
// ---------------------------------------------------------------------------
__global__ void gate_k(const float* __restrict__ hn2, const float* __restrict__ gw,
                       const float* __restrict__ gb, const float* __restrict__ grw,
                       float* __restrict__ g)
{
    const int n    = blockIdx.x * 4 + (threadIdx.x >> 5);
    const int lane = threadIdx.x & 31;
    const float* xr = hn2 + (size_t)n * D_;

    float acc[E_];
    #pragma unroll
    for (int e = 0; e < E_; e++) acc[e] = 0.f;
    for (int d = lane; d < D_; d += 32) {
        const float xv = xr[d];
        #pragma unroll
        for (int e = 0; e < E_; e++) acc[e] += xv * gw[e * D_ + d];
    }
    #pragma unroll
    for (int e = 0; e < E_; e++)
        #pragma unroll
        for (int off = 16; off > 0; off >>= 1)
            acc[e] += __shfl_xor_sync(0xffffffffu, acc[e], off);

    if (lane == 0) {
        float l[E_], ss = 0.f;
        #pragma unroll
        for (int e = 0; e < E_; e++) { l[e] = acc[e] + gb[e]; ss += l[e] * l[e]; }
        const float inv = rsqrtf(ss / (float)E_ + 1.1920929e-7f);  // fp32 eps
        float m = -INFINITY;
        #pragma unroll
        for (int e = 0; e < E_; e++) {
            l[e] = l[e] * inv * grw[e] * 2.0f;   // rmsnorm weight, then /TEMP(0.5)
            m = fmaxf(m, l[e]);
        }
        float sum = 0.f, mx = 0.f;
        #pragma unroll
        for (int e = 0; e < E_; e++) {
            const float ex = __expf(l[e] - m);
            sum += ex;
            mx = fmaxf(mx, ex);
        }
        const float top = mx / sum;
        g[n] = top / (top + 1e-6f);
    }
}

// ---------------------------------------------------------------------------
// SwiGLU: act[n, e*2048+f] = h1[n, e*4096+f] * silu(h1[n, e*4096+2048+f])
// ---------------------------------------------------------------------------
__global__ void swiglu_k(const float* __restrict__ h1, float* __restrict__ act)
{
    const size_t idx = (size_t)blockIdx.x * blockDim.x + threadIdx.x;
    const size_t total = (size_t)NTOK * E_ * FF2_;
    if (idx >= total) return;
    const size_t n = idx >> 14;            // / 16384
    const int    c = (int)(idx & 16383);
    const int    e = c >> 11;              // / 2048
    const int    f = c & 2047;
    const float* base = h1 + n * (size_t)(E_ * FF1_) + (size_t)e * FF1_ + f;
    const float a = base[0];
    const float b = base[FF2_];
    act[idx] = a * b / (1.f + __expf(-b));
}

// ---------------------------------------------------------------------------
// Launch
// ---------------------------------------------------------------------------
extern "C" void kernel_launch(void* const* d_in, const int* in_sizes, int n_in,
                              void* d_out, int out_size)
{
    const float* x      = (const float*)d_in[0];
    const float* w_qkv  = (const float*)d_in[1];
    const float* w_out  = (const float*)d_in[2];
    const float* norm1w = (const float*)d_in[3];
    const float* norm2w = (const float*)d_in[4];
    const float* gate_w = (const float*)d_in[5];
    const float* gate_b = (const float*)d_in[6];
    const float* gate_rw= (const float*)d_in[7];
    const float* w1     = (const float*)d_in[8];
    const float* w2     = (const float*)d_in[9];
    float* out = (float*)d_out;

    float *hn1, *qkv, *scores, *attno, *h2, *hn2, *gate, *h1, *act;
    cudaGetSymbolAddress((void**)&hn1,    g_hn1);
    cudaGetSymbolAddress((void**)&qkv,    g_qkv);
    cudaGetSymbolAddress((void**)&scores, g_scores);
    cudaGetSymbolAddress((void**)&attno,  g_attno);
    cudaGetSymbolAddress((void**)&h2,     g_h2);
    cudaGetSymbolAddress((void**)&hn2,    g_hn2);
    cudaGetSymbolAddress((void**)&gate,   g_gate);
    cudaGetSymbolAddress((void**)&h1,     g_h1);
    cudaGetSymbolAddress((void**)&act,    g_act);

    // 1) rmsnorm1
    rmsnorm_k<<<NTOK, 256>>>(x, norm1w, hn1, 1e-8f);

    // 2) QKV: [4096,1024] x w_qkv^T[1024,3072] -> qkv [4096,3072]   (NT)
    gemm_k<0, true><<<dim3(3 * D_ / 128, NTOK / 128, 1), 256>>>(
        hn1, w_qkv, qkv, nullptr, nullptr,
        NTOK, 3 * D_, D_, D_, D_, 3 * D_,
        1, 0, 0, 0, 0, 0, 0, 1.f);

    // 3) scores[b,h] = Q K^T / 8   (NT, batched over 64 (b,h) pairs)
    gemm_k<0, true><<<dim3(S_ / 128, S_ / 128, B_ * H_), 256>>>(
        qkv, qkv + D_, scores, nullptr, nullptr,
        S_, S_, DH_, 3 * D_, 3 * D_, S_,
        H_,
        (long)S_ * 3 * D_, (long)DH_,          // A: b-stride, h-stride
        (long)S_ * 3 * D_, (long)DH_,          // B: same
        (long)H_ * S_ * S_, (long)S_ * S_,     // C: b-stride, h-stride
        0.125f);

    // 4) softmax over k
    softmax_k<<<B_ * H_ * S_, 256>>>(scores);

    // 5) O[b,h] = P V   (NN, batched)
    gemm_k<0, false><<<dim3(1, S_ / 128, B_ * H_), 256>>>(
        scores, qkv + 2 * D_, attno, nullptr, nullptr,
        S_, DH_, S_, S_, 3 * D_, D_,
        H_,
        (long)H_ * S_ * S_, (long)S_ * S_,     // A (P)
        (long)S_ * 3 * D_, (long)DH_,          // B (V)
        (long)S_ * D_, (long)DH_,              // C (O): token rows, head cols
        1.f);

    // 6) h2 = x + O w_out^T   (NT, residual epilogue)
    gemm_k<1, true><<<dim3(D_ / 128, NTOK / 128, 1), 256>>>(
        attno, w_out, h2, x, nullptr,
        NTOK, D_, D_, D_, D_, D_,
        1, 0, 0, 0, 0, 0, 0, 1.f);

    // 7) rmsnorm2
    rmsnorm_k<<<NTOK, 256>>>(h2, norm2w, hn2, 1e-8f);

    // 8) gating
    gate_k<<<NTOK / 4, 128>>>(hn2, gate_w, gate_b, gate_rw, gate);

    // 9) MoE GEMM1: per-expert [4096,1024] x [1024,4096] -> h1 [4096, 8*4096]
    //    (NN, batched over experts; C column-offset per expert)
    gemm_k<0, false><<<dim3(FF1_ / 128, NTOK / 128, E_), 256>>>(
        hn2, w1, h1, nullptr, nullptr,
        NTOK, FF1_, D_, D_, FF1_, E_ * FF1_,
        1,
        0, 0,
        (long)D_ * FF1_, 0,                    // B: expert stride
        (long)FF1_, 0,                         // C: expert column offset
        1.f);

    // 10) SwiGLU -> act [4096, 8*2048]
    {
        const size_t total = (size_t)NTOK * E_ * FF2_;
        swiglu_k<<<(unsigned)((total + 255) / 256), 256>>>(h1, act);
    }

    // 11) MoE GEMM2: out = h2 + (act [4096,16384] x w2_flat [16384,1024]) * g[n]
    gemm_k<2, false><<<dim3(D_ / 128, NTOK / 128, 1), 256>>>(
        act, w2, out, h2, gate,
        NTOK, D_, E_ * FF2_, E_ * FF2_, D_, D_,
        1, 0, 0, 0, 0, 0, 0, 1.f);

    (void)in_sizes; (void)n_in; (void)out_size;
}

// round 2
// speedup vs baseline: 1.0002x; 1.0002x over previous
#include <cuda_runtime.h>
#include <cmath>

// ---------------------------------------------------------------------------
// Problem constants
// ---------------------------------------------------------------------------
static constexpr int B_   = 4;
static constexpr int S_   = 1024;
static constexpr int D_   = 1024;
static constexpr int H_   = 16;
static constexpr int DH_  = 64;       // D/H
static constexpr int E_   = 8;
static constexpr int FF1_ = 4096;
static constexpr int FF2_ = 2048;
static constexpr int NTOK = B_ * S_;  // 4096

// ---------------------------------------------------------------------------
// Scratch (static device globals; allocation inside kernel_launch is banned)
// ---------------------------------------------------------------------------
__device__ float g_hn1  [(size_t)NTOK * D_];            //  16 MB
__device__ float g_qkv  [(size_t)NTOK * 3 * D_];        //  50 MB
__device__ float g_scores[(size_t)B_ * H_ * S_ * S_];   // 268 MB (also holds P)
__device__ float g_attno[(size_t)NTOK * D_];            //  16 MB
__device__ float g_h2   [(size_t)NTOK * D_];            //  16 MB  x + attn
__device__ float g_hn2  [(size_t)NTOK * D_];            //  16 MB
__device__ float g_gate [NTOK];
__device__ float g_h1   [(size_t)NTOK * E_ * FF1_];     // 537 MB
__device__ float g_act  [(size_t)NTOK * E_ * FF2_];     // 268 MB

// ---------------------------------------------------------------------------
// Generic tiled fp32 GEMM:  C = alpha * A(MxK) * B  (+ epilogue)
//   BT=true : B is [N,K] row-major (C[m,n] = sum_k A[m,k]*B[n,k])
//   BT=false: B is [K,N] row-major
//   Two-level batch offset: bz -> (zb = bz/zDiv, zh = bz%zDiv)
//   EPI 0: C = alpha*acc
//   EPI 1: C = alpha*acc + Res            (Res same layout/offset as C)
//   EPI 2: C = Res + acc * Gvec[row]
// ---------------------------------------------------------------------------
template<int EPI, bool BT>
__global__ void __launch_bounds__(256)
gemm_k(const float* __restrict__ A, const float* __restrict__ B,
       float* __restrict__ C, const float* __restrict__ Res,
       const float* __restrict__ Gvec,
       int M, int N, int K, int lda, int ldb, int ldc,
       int zDiv, long sA1, long sA2, long sB1, long sB2, long sC1, long sC2,
       float alpha)
{
    constexpr int BM = 128, BN = 128, BK = 16;
    __shared__ float As[BK][BM];
    __shared__ float Bs[BK][BN];

    const int bz = blockIdx.z;
    const int zb = bz / zDiv;
    const int zh = bz - zb * zDiv;
    A += (size_t)zb * sA1 + (size_t)zh * sA2;
    B += (size_t)zb * sB1 + (size_t)zh * sB2;
    const size_t coff = (size_t)zb * sC1 + (size_t)zh * sC2;
    C += coff;
    if (EPI == 1 || EPI == 2) Res += coff;

    const int bm  = blockIdx.y * BM;
    const int bn  = blockIdx.x * BN;
    const int tid = threadIdx.x;
    const int tx  = tid & 15;        // 0..15
    const int ty  = tid >> 4;        // 0..15

    // A / NT-B load mapping: 128 rows x 16 k, 8 floats per thread
    const int arow = tid >> 1;            // 0..127
    const int akc  = (tid & 1) * 8;       // 0 or 8
    // NN-B load mapping: 16 k-rows x 128 n-cols
    const int bkr  = tid >> 4;            // 0..15
    const int bnc  = (tid & 15) * 8;      // 0..120

    float acc[8][8];
    #pragma unroll
    for (int i = 0; i < 8; i++)
        #pragma unroll
        for (int j = 0; j < 8; j++) acc[i][j] = 0.f;

    for (int k0 = 0; k0 < K; k0 += BK) {
        // ---- load A tile (K is always a multiple of 16; M a multiple of 128)
        {
            const int gm = bm + arow;
            const float* ap = A + (size_t)gm * lda + k0 + akc;
            float4 v0 = *(const float4*)ap;
            float4 v1 = *(const float4*)(ap + 4);
            As[akc + 0][arow] = v0.x; As[akc + 1][arow] = v0.y;
            As[akc + 2][arow] = v0.z; As[akc + 3][arow] = v0.w;
            As[akc + 4][arow] = v1.x; As[akc + 5][arow] = v1.y;
            As[akc + 6][arow] = v1.z; As[akc + 7][arow] = v1.w;
        }
        // ---- load B tile
        if (BT) {
            const int gn = bn + arow;
            if (gn < N) {
                const float* bp = B + (size_t)gn * ldb + k0 + akc;
                float4 v0 = *(const float4*)bp;
                float4 v1 = *(const float4*)(bp + 4);
                Bs[akc + 0][arow] = v0.x; Bs[akc + 1][arow] = v0.y;
                Bs[akc + 2][arow] = v0.z; Bs[akc + 3][arow] = v0.w;
                Bs[akc + 4][arow] = v1.x; Bs[akc + 5][arow] = v1.y;
                Bs[akc + 6][arow] = v1.z; Bs[akc + 7][arow] = v1.w;
            } else {
                #pragma unroll
                for (int i = 0; i < 8; i++) Bs[akc + i][arow] = 0.f;
            }
        } else {
            const int gk = k0 + bkr;
            const int gn = bn + bnc;
            const float* bp = B + (size_t)gk * ldb + gn;
            if (gn + 7 < N) {
                *(float4*)&Bs[bkr][bnc]     = *(const float4*)bp;
                *(float4*)&Bs[bkr][bnc + 4] = *(const float4*)(bp + 4);
            } else {
                #pragma unroll
                for (int i = 0; i < 8; i++)
                    Bs[bkr][bnc + i] = (gn + i < N) ? bp[i] : 0.f;
            }
        }
        __syncthreads();

        // ---- compute
        #pragma unroll
        for (int kk = 0; kk < BK; kk++) {
            float4 a0 = *(const float4*)&As[kk][ty * 8];
            float4 a1 = *(const float4*)&As[kk][ty * 8 + 4];
            float4 b0 = *(const float4*)&Bs[kk][tx * 8];
            float4 b1 = *(const float4*)&Bs[kk][tx * 8 + 4];
            float a[8] = {a0.x, a0.y, a0.z, a0.w, a1.x, a1.y, a1.z, a1.w};
            float b[8] = {b0.x, b0.y, b0.z, b0.w, b1.x, b1.y, b1.z, b1.w};
            #pragma unroll
            for (int i = 0; i < 8; i++)
                #pragma unroll
                for (int j = 0; j < 8; j++)
                    acc[i][j] += a[i] * b[j];
        }
        __syncthreads();
    }

    // ---- epilogue
    #pragma unroll
    for (int i = 0; i < 8; i++) {
        const int gm = bm + ty * 8 + i;
        if (gm >= M) continue;
        #pragma unroll
        for (int j = 0; j < 8; j++) {
            const int gn = bn + tx * 8 + j;
            if (gn >= N) continue;
            const size_t idx = (size_t)gm * ldc + gn;
            float v;
            if (EPI == 0)      v = alpha * acc[i][j];
            else if (EPI == 1) v = alpha * acc[i][j] + Res[idx];
            else               v = Res[idx] + acc[i][j] * Gvec[gm];
            C[idx] = v;
        }
    }
}

// ---------------------------------------------------------------------------
// RMSNorm over rows of length 1024
// ---------------------------------------------------------------------------
__global__ void rmsnorm_k(const float* __restrict__ x, const float* __restrict__ w,
                          float* __restrict__ y, float eps)
{
    const int row = blockIdx.x;
    const float* xr = x + (size_t)row * D_;
    float s = 0.f;
    for (int i = threadIdx.x; i < D_; i += 256) { float v = xr[i]; s += v * v; }
    __shared__ float red[256];
    red[threadIdx.x] = s;
    __syncthreads();
    for (int off = 128; off > 0; off >>= 1) {
        if (threadIdx.x < off) red[threadIdx.x] += red[threadIdx.x + off];
        __syncthreads();
    }
    const float inv = rsqrtf(red[0] / (float)D_ + eps);
    float* yr = y + (size_t)row * D_;
    for (int i = threadIdx.x; i < D_; i += 256) yr[i] = xr[i] * inv * w[i];
}

// ---------------------------------------------------------------------------
// Row softmax over 1024-length rows (in place, for attention scores)
// ---------------------------------------------------------------------------
__global__ void softmax_k(float* __restrict__ sc)
{
    float* p = sc + (size_t)blockIdx.x * S_;
    const int t = threadIdx.x;
    __shared__ float red[256];

    float m = -INFINITY;
    for (int i = t; i < S_; i += 256) m = fmaxf(m, p[i]);
    red[t] = m; __syncthreads();
    for (int off = 128; off > 0; off >>= 1) {
        if (t < off) red[t] = fmaxf(red[t], red[t + off]);
        __syncthreads();
    }
    m = red[0];
    __syncthreads();

    float sum = 0.f;
    for (int i = t; i < S_; i += 256) {
        float e = __expf(p[i] - m);
        p[i] = e;
        sum += e;
    }
    red[t] = sum; __syncthreads();
    for (int off = 128; off > 0; off >>= 1) {
        if (t < off) red[t] += red[t + off];
        __syncthreads();
    }
    const float inv = 1.f / red[0];
    for (int i = t; i < S_; i += 256) p[i] *= inv;
}

// ---------------------------------------------------------------------------
// Gating: logits -> rmsnorm(E) -> softmax(/0.5) -> top1 -> g/(g+1e-6)
// One warp per token.
// ---------------------------------------------------------------------------
__global__ void gate_k(const float* __restrict__ hn2, const float* __restrict__ gw,
                       const float* __restrict__ gb, const float* __restrict__ grw,
                       float* __restrict__ g)
{
    const int n    = blockIdx.x * 4 + (threadIdx.x >> 5);
    const int lane = threadIdx.x & 31;
    const float* xr = hn2 + (size_t)n * D_;

    float acc[E_];
    #pragma unroll
    for (int e = 0; e < E_; e++) acc[e] = 0.f;
    for (int d = lane; d < D_; d += 32) {
        const float xv = xr[d];
        #pragma unroll
        for (int e = 0; e < E_; e++) acc[e] += xv * gw[e * D_ + d];
    }
    #pragma unroll
    for (int e = 0; e < E_; e++)
        #pragma unroll
        for (int off = 16; off > 0; off >>= 1)
            acc[e] += __shfl_xor_sync(0xffffffffu, acc[e], off);

    if (lane == 0) {
        float l[E_], ss = 0.f;
        #pragma unroll
        for (int e = 0; e < E_; e++) { l[e] = acc[e] + gb[e]; ss += l[e] * l[e]; }
        const float inv = rsqrtf(ss / (float)E_ + 1.1920929e-7f);  // fp32 eps
        float m = -INFINITY;
        #pragma unroll
        for (int e = 0; e < E_; e++) {
            l[e] = l[e] * inv * grw[e] * 2.0f;   // rmsnorm weight, then /TEMP(0.5)
            m = fmaxf(m, l[e]);
        }
        float sum = 0.f, mx = 0.f;
        #pragma unroll
        for (int e = 0; e < E_; e++) {
            const float ex = __expf(l[e] - m);
            sum += ex;
            mx = fmaxf(mx, ex);
        }
        const float top = mx / sum;
        g[n] = top / (top + 1e-6f);
    }
}

// ---------------------------------------------------------------------------
// SwiGLU: act[n, e*2048+f] = h1[n, e*4096+f] * silu(h1[n, e*4096+2048+f])
// ---------------------------------------------------------------------------
__global__ void swiglu_k(const float* __restrict__ h1, float* __restrict__ act)
{
    const size_t idx = (size_t)blockIdx.x * blockDim.x + threadIdx.x;
    const size_t total = (size_t)NTOK * E_ * FF2_;
    if (idx >= total) return;
    const size_t n = idx >> 14;            // / 16384
    const int    c = (int)(idx & 16383);
    const int    e = c >> 11;              // / 2048
    const int    f = c & 2047;
    const float* base = h1 + n * (size_t)(E_ * FF1_) + (size_t)e * FF1_ + f;
    const float a = base[0];
    const float b = base[FF2_];
    act[idx] = a * b / (1.f + __expf(-b));
}

// ---------------------------------------------------------------------------
// Launch
// ---------------------------------------------------------------------------
extern "C" void kernel_launch(void* const* d_in, const int* in_sizes, int n_in,
                              void* d_out, int out_size)
{
    const float* x      = (const float*)d_in[0];
    const float* w_qkv  = (const float*)d_in[1];
    const float* w_out  = (const float*)d_in[2];
    const float* norm1w = (const float*)d_in[3];
    const float* norm2w = (const float*)d_in[4];
    const float* gate_w = (const float*)d_in[5];
    const float* gate_b = (const float*)d_in[6];
    const float* gate_rw= (const float*)d_in[7];
    const float* w1     = (const float*)d_in[8];
    const float* w2     = (const float*)d_in[9];
    float* out = (float*)d_out;

    float *hn1, *qkv, *scores, *attno, *h2, *hn2, *gate, *h1, *act;
    cudaGetSymbolAddress((void**)&hn1,    g_hn1);
    cudaGetSymbolAddress((void**)&qkv,    g_qkv);
    cudaGetSymbolAddress((void**)&scores, g_scores);
    cudaGetSymbolAddress((void**)&attno,  g_attno);
    cudaGetSymbolAddress((void**)&h2,     g_h2);
    cudaGetSymbolAddress((void**)&hn2,    g_hn2);
    cudaGetSymbolAddress((void**)&gate,   g_gate);
    cudaGetSymbolAddress((void**)&h1,     g_h1);
    cudaGetSymbolAddress((void**)&act,    g_act);

    // 1) rmsnorm1
    rmsnorm_k<<<NTOK, 256>>>(x, norm1w, hn1, 1e-8f);

    // 2) QKV: [4096,1024] x w_qkv^T[1024,3072] -> qkv [4096,3072]   (NT)
    gemm_k<0, true><<<dim3(3 * D_ / 128, NTOK / 128, 1), 256>>>(
        hn1, w_qkv, qkv, nullptr, nullptr,
        NTOK, 3 * D_, D_, D_, D_, 3 * D_,
        1, 0, 0, 0, 0, 0, 0, 1.f);

    // 3) scores[b,h] = Q K^T / 8   (NT, batched over 64 (b,h) pairs)
    gemm_k<0, true><<<dim3(S_ / 128, S_ / 128, B_ * H_), 256>>>(
        qkv, qkv + D_, scores, nullptr, nullptr,
        S_, S_, DH_, 3 * D_, 3 * D_, S_,
        H_,
        (long)S_ * 3 * D_, (long)DH_,          // A: b-stride, h-stride
        (long)S_ * 3 * D_, (long)DH_,          // B: same
        (long)H_ * S_ * S_, (long)S_ * S_,     // C: b-stride, h-stride
        0.125f);

    // 4) softmax over k
    softmax_k<<<B_ * H_ * S_, 256>>>(scores);

    // 5) O[b,h] = P V   (NN, batched)
    gemm_k<0, false><<<dim3(1, S_ / 128, B_ * H_), 256>>>(
        scores, qkv + 2 * D_, attno, nullptr, nullptr,
        S_, DH_, S_, S_, 3 * D_, D_,
        H_,
        (long)H_ * S_ * S_, (long)S_ * S_,     // A (P)
        (long)S_ * 3 * D_, (long)DH_,          // B (V)
        (long)S_ * D_, (long)DH_,              // C (O): token rows, head cols
        1.f);

    // 6) h2 = x + O w_out^T   (NT, residual epilogue)
    gemm_k<1, true><<<dim3(D_ / 128, NTOK / 128, 1), 256>>>(
        attno, w_out, h2, x, nullptr,
        NTOK, D_, D_, D_, D_, D_,
        1, 0, 0, 0, 0, 0, 0, 1.f);

    // 7) rmsnorm2
    rmsnorm_k<<<NTOK, 256>>>(h2, norm2w, hn2, 1e-8f);

    // 8) gating
    gate_k<<<NTOK / 4, 128>>>(hn2, gate_w, gate_b, gate_rw, gate);

    // 9) MoE GEMM1: per-expert [4096,1024] x [1024,4096] -> h1 [4096, 8*4096]
    //    (NN, batched over experts; C column-offset per expert)
    gemm_k<0, false><<<dim3(FF1_ / 128, NTOK / 128, E_), 256>>>(
        hn2, w1, h1, nullptr, nullptr,
        NTOK, FF1_, D_, D_, FF1_, E_ * FF1_,
        1,
        0, 0,
        (long)D_ * FF1_, 0,                    // B: expert stride
        (long)FF1_, 0,                         // C: expert column offset
        1.f);

    // 10) SwiGLU -> act [4096, 8*2048]
    {
        const size_t total = (size_t)NTOK * E_ * FF2_;
        swiglu_k<<<(unsigned)((total + 255) / 256), 256>>>(h1, act);
    }

    // 11) MoE GEMM2: out = h2 + (act [4096,16384] x w2_flat [16384,1024]) * g[n]
    gemm_k<2, false><<<dim3(D_ / 128, NTOK / 128, 1), 256>>>(
        act, w2, out, h2, gate,
        NTOK, D_, E_ * FF2_, E_ * FF2_, D_, D_,
        1, 0, 0, 0, 0, 0, 0, 1.f);

    (void)in_sizes; (void)n_in; (void)out_size;
}

// round 4
// speedup vs baseline: 3.4227x; 3.4221x over previous
#include <cuda_runtime.h>
#include <cstdint>
#include <cmath>

// ===========================================================================
// Problem constants
// ===========================================================================
static constexpr int B_   = 4;
static constexpr int S_   = 1024;
static constexpr int D_   = 1024;
static constexpr int H_   = 16;
static constexpr int DH_  = 64;
static constexpr int E_   = 8;
static constexpr int FF1_ = 4096;
static constexpr int FF2_ = 2048;
static constexpr int NTOK = B_ * S_;        // 4096
static constexpr int KMOE2 = E_ * FF2_;     // 16384

// ===========================================================================
// Scratch
// ===========================================================================
__device__ float g_hn1   [(size_t)NTOK * D_];
__device__ float g_wqkvr [(size_t)3 * D_ * D_];
__device__ float g_woutr [(size_t)D_ * D_];
__device__ float g_qkv   [(size_t)NTOK * 3 * D_];
__device__ float g_vt    [(size_t)B_ * H_ * DH_ * S_];
__device__ float g_scores[(size_t)B_ * H_ * S_ * S_];
__device__ float g_attno [(size_t)NTOK * D_];
__device__ float g_h2    [(size_t)NTOK * D_];
__device__ float g_hn2   [(size_t)NTOK * D_];
__device__ float g_gate  [NTOK];
__device__ float g_w1t   [(size_t)E_ * FF1_ * D_];
__device__ float g_w2t   [(size_t)D_ * KMOE2];
__device__ float g_h1    [(size_t)E_ * NTOK * FF1_];
__device__ float g_act   [(size_t)NTOK * KMOE2];

// ===========================================================================
// Helpers
// ===========================================================================
__device__ __forceinline__ uint32_t smem_u32(const void* p) {
    uint32_t a;
    asm("{ .reg .u64 t; cvta.to.shared.u64 t, %1; cvt.u32.u64 %0, t; }" : "=r"(a) : "l"(p));
    return a;
}
__device__ __forceinline__ float to_tf32(float x) {
    uint32_t u;
    asm("cvt.rna.tf32.f32 %0, %1;" : "=r"(u) : "f"(x));
    return __uint_as_float(u);
}

#define CP16(dst, src) \
    asm volatile("cp.async.cg.shared.global [%0], [%1], 16;" :: "r"(dst), "l"(src))
#define CP_COMMIT()  asm volatile("cp.async.commit_group;" ::: "memory")
#define CP_WAIT1()   asm volatile("cp.async.wait_group 1;" ::: "memory")
#define CP_WAIT0()   asm volatile("cp.async.wait_group 0;" ::: "memory")

__device__ __forceinline__ void mma_tf32(float& c0, float& c1, float& c2, float& c3,
                                         uint32_t a0, uint32_t a1, uint32_t a2, uint32_t a3,
                                         uint32_t b0, uint32_t b1)
{
    asm volatile(
        "mma.sync.aligned.m16n8k8.row.col.f32.tf32.tf32.f32 "
        "{%0,%1,%2,%3}, {%4,%5,%6,%7}, {%8,%9}, {%0,%1,%2,%3};"
        : "+f"(c0), "+f"(c1), "+f"(c2), "+f"(c3)
        : "r"(a0), "r"(a1), "r"(a2), "r"(a3), "r"(b0), "r"(b1));
}

// ===========================================================================
// mma.sync tf32 NT GEMM: C[M,N] = alpha * A[M,K](K-major) * B[N,K](K-major)^T
//   EPI 0: C = alpha*acc (optionally tf32-rounded)
//   EPI 1: C = acc + Res
//   EPI 2: C = Res + acc * Gvec[row]
// Tiles: 128 x BN x 32, 8 warps (4m x 2n), warp tile 32 x BN/2.
// SMEM: As[128][36], Bs[BN][36] (stride-36 pad => conflict-free fragments),
// 2-stage cp.async double buffer.
// All M, N, K are multiples of 128 / BN / 32 respectively (asserted by caller).
// ===========================================================================
template<int EPI, int BN, bool ROUND>
__global__ void __launch_bounds__(256)
mma_gemm(const float* __restrict__ A, const float* __restrict__ B,
         float* __restrict__ C, const float* __restrict__ Res,
         const float* __restrict__ Gvec,
         int M, int N, int K, int lda, int ldb, int ldc,
         int zDiv, long sA1, long sA2, long sB1, long sB2, long sC1, long sC2,
         float alpha)
{
    constexpr int NT = BN / 16;          // n-tiles (8 cols each) per warp
    constexpr int ASTG = 128 * 36;       // floats per A stage
    constexpr int BSTG = BN * 36;        // floats per B stage

    extern __shared__ __align__(16) float sm[];
    const uint32_t sbase = smem_u32(sm);
    const int tid = threadIdx.x, wid = tid >> 5, lane = tid & 31;
    const int warp_m = wid & 3, warp_n = wid >> 2;

    const int bz = blockIdx.z;
    const int zb = bz / zDiv, zh = bz - zb * zDiv;
    A += (size_t)zb * sA1 + (size_t)zh * sA2;
    B += (size_t)zb * sB1 + (size_t)zh * sB2;
    const size_t coff = (size_t)zb * sC1 + (size_t)zh * sC2;
    C += coff;
    if (EPI == 1 || EPI == 2) Res += coff;

    const int bm = blockIdx.y * 128;
    const int bn = blockIdx.x * BN;
    A += (size_t)bm * lda;
    B += (size_t)bn * ldb;

    const int nk = K / 32;

    auto loadA = [&](int s, int kt) {
        const float* base = A + kt * 32;
        const uint32_t dbase = sbase + (uint32_t)(s * ASTG) * 4;
        #pragma unroll
        for (int i = 0; i < 4; i++) {
            const int c = tid + i * 256;        // 0..1023
            const int row = c >> 3, kc = c & 7;
            CP16(dbase + (uint32_t)row * 144 + (uint32_t)kc * 16,
                 base + (size_t)row * lda + kc * 4);
        }
    };
    auto loadB = [&](int s, int kt) {
        const float* base = B + kt * 32;
        const uint32_t dbase = sbase + (uint32_t)(2 * ASTG + s * BSTG) * 4;
        #pragma unroll
        for (int i = 0; i < BN / 32; i++) {
            const int c = tid + i * 256;
            const int row = c >> 3, kc = c & 7;
            CP16(dbase + (uint32_t)row * 144 + (uint32_t)kc * 16,
                 base + (size_t)row * ldb + kc * 4);
        }
    };

    float acc[2][NT][4];
    #pragma unroll
    for (int mi = 0; mi < 2; mi++)
        #pragma unroll
        for (int ni = 0; ni < NT; ni++)
            #pragma unroll
            for (int j = 0; j < 4; j++) acc[mi][ni][j] = 0.f;

    loadA(0, 0); loadB(0, 0); CP_COMMIT();

    const int lq = lane >> 2;          // 0..7
    const int lr = lane & 3;           // 0..3

    for (int kt = 0; kt < nk; kt++) {
        const int cs = kt & 1;
        if (kt + 1 < nk) {
            loadA(cs ^ 1, kt + 1); loadB(cs ^ 1, kt + 1); CP_COMMIT();
            CP_WAIT1();
        } else {
            CP_WAIT0();
        }
        __syncthreads();

        const float* As = sm + cs * ASTG;
        const float* Bs = sm + 2 * ASTG + cs * BSTG;

        #pragma unroll
        for (int ks = 0; ks < 4; ks++) {
            const int kk = ks * 8 + lr;
            uint32_t a[2][4];
            #pragma unroll
            for (int mi = 0; mi < 2; mi++) {
                const int r0 = warp_m * 32 + mi * 16 + lq;
                a[mi][0] = __float_as_uint(As[r0 * 36 + kk]);
                a[mi][1] = __float_as_uint(As[(r0 + 8) * 36 + kk]);
                a[mi][2] = __float_as_uint(As[r0 * 36 + kk + 4]);
                a[mi][3] = __float_as_uint(As[(r0 + 8) * 36 + kk + 4]);
            }
            uint32_t b[NT][2];
            #pragma unroll
            for (int ni = 0; ni < NT; ni++) {
                const int n0 = warp_n * (BN / 2) + ni * 8 + lq;
                b[ni][0] = __float_as_uint(Bs[n0 * 36 + kk]);
                b[ni][1] = __float_as_uint(Bs[n0 * 36 + kk + 4]);
            }
            #pragma unroll
            for (int mi = 0; mi < 2; mi++)
                #pragma unroll
                for (int ni = 0; ni < NT; ni++)
                    mma_tf32(acc[mi][ni][0], acc[mi][ni][1], acc[mi][ni][2], acc[mi][ni][3],
                             a[mi][0], a[mi][1], a[mi][2], a[mi][3],
                             b[ni][0], b[ni][1]);
        }
        __syncthreads();
    }

    // ---- epilogue
    #pragma unroll
    for (int mi = 0; mi < 2; mi++) {
        const int row0 = bm + warp_m * 32 + mi * 16 + lq;
        float gv0 = 1.f, gv1 = 1.f;
        if (EPI == 2) { gv0 = Gvec[row0]; gv1 = Gvec[row0 + 8]; }
        #pragma unroll
        for (int ni = 0; ni < NT; ni++) {
            const int col = bn + warp_n * (BN / 2) + ni * 8 + lr * 2;
            const size_t i0 = (size_t)row0 * ldc + col;
            const size_t i1 = (size_t)(row0 + 8) * ldc + col;
            float2 o0, o1;
            if (EPI == 0) {
                o0.x = alpha * acc[mi][ni][0]; o0.y = alpha * acc[mi][ni][1];
                o1.x = alpha * acc[mi][ni][2]; o1.y = alpha * acc[mi][ni][3];
                if (ROUND) {
                    o0.x = to_tf32(o0.x); o0.y = to_tf32(o0.y);
                    o1.x = to_tf32(o1.x); o1.y = to_tf32(o1.y);
                }
            } else if (EPI == 1) {
                float2 r0 = *(const float2*)&Res[i0];
                float2 r1 = *(const float2*)&Res[i1];
                o0.x = acc[mi][ni][0] + r0.x; o0.y = acc[mi][ni][1] + r0.y;
                o1.x = acc[mi][ni][2] + r1.x; o1.y = acc[mi][ni][3] + r1.y;
            } else {
                float2 r0 = *(const float2*)&Res[i0];
                float2 r1 = *(const float2*)&Res[i1];
                o0.x = r0.x + acc[mi][ni][0] * gv0; o0.y = r0.y + acc[mi][ni][1] * gv0;
                o1.x = r1.x + acc[mi][ni][2] * gv1; o1.y = r1.y + acc[mi][ni][3] * gv1;
            }
            *(float2*)&C[i0] = o0;
            *(float2*)&C[i1] = o1;
        }
    }
}

// ===========================================================================
// RMSNorm (rounds output to tf32)
// ===========================================================================
__global__ void rmsnorm_k(const float* __restrict__ x, const float* __restrict__ w,
                          float* __restrict__ y, float eps)
{
    const int row = blockIdx.x;
    const float* xr = x + (size_t)row * D_;
    float v[4];
    float s = 0.f;
    #pragma unroll
    for (int i = 0; i < 4; i++) { v[i] = xr[threadIdx.x + 256 * i]; s += v[i] * v[i]; }
    #pragma unroll
    for (int o = 16; o > 0; o >>= 1) s += __shfl_xor_sync(~0u, s, o);
    __shared__ float red[8];
    if ((threadIdx.x & 31) == 0) red[threadIdx.x >> 5] = s;
    __syncthreads();
    if (threadIdx.x < 8) {
        float t = red[threadIdx.x];
        #pragma unroll
        for (int o = 4; o > 0; o >>= 1) t += __shfl_xor_sync(0xffu, t, o);
        if (threadIdx.x == 0) red[0] = t;
    }
    __syncthreads();
    const float inv = rsqrtf(red[0] / (float)D_ + eps);
    float* yr = y + (size_t)row * D_;
    #pragma unroll
    for (int i = 0; i < 4; i++)
        yr[threadIdx.x + 256 * i] = to_tf32(v[i] * inv * w[threadIdx.x + 256 * i]);
}

// ===========================================================================
// Softmax over 1024-length rows, register-resident, rounds output to tf32
// ===========================================================================
__global__ void softmax_k(float* __restrict__ sc)
{
    float* p = sc + (size_t)blockIdx.x * S_;
    const int t = threadIdx.x;
    float v[4];
    #pragma unroll
    for (int i = 0; i < 4; i++) v[i] = p[t + 256 * i];
    float m = fmaxf(fmaxf(v[0], v[1]), fmaxf(v[2], v[3]));
    #pragma unroll
    for (int o = 16; o > 0; o >>= 1) m = fmaxf(m, __shfl_xor_sync(~0u, m, o));
    __shared__ float red[8];
    if ((t & 31) == 0) red[t >> 5] = m;
    __syncthreads();
    float mm = fmaxf(fmaxf(red[0], red[1]), fmaxf(red[2], red[3]));
    mm = fmaxf(mm, fmaxf(fmaxf(red[4], red[5]), fmaxf(red[6], red[7])));
    float s = 0.f;
    #pragma unroll
    for (int i = 0; i < 4; i++) { v[i] = __expf(v[i] - mm); s += v[i]; }
    #pragma unroll
    for (int o = 16; o > 0; o >>= 1) s += __shfl_xor_sync(~0u, s, o);
    __syncthreads();
    if ((t & 31) == 0) red[t >> 5] = s;
    __syncthreads();
    float ss = red[0] + red[1] + red[2] + red[3] + red[4] + red[5] + red[6] + red[7];
    const float inv = 1.f / ss;
    #pragma unroll
    for (int i = 0; i < 4; i++) p[t + 256 * i] = to_tf32(v[i] * inv);
}

// ===========================================================================
// Gating — computed from raw h2 (fp32, no tf32 rounding in this path):
// hn2 = h2 * rsqrt(mean(h2^2)+1e-8) * norm2w ;  logits = hn2 @ gw^T + gb
// then rmsnorm over E, softmax(/0.5), top1, g/(g+1e-6).
// ===========================================================================
__global__ void gate_k(const float* __restrict__ h2, const float* __restrict__ n2w,
                       const float* __restrict__ gw,
                       const float* __restrict__ gb, const float* __restrict__ grw,
                       float* __restrict__ g)
{
    const int n    = blockIdx.x * 4 + (threadIdx.x >> 5);
    const int lane = threadIdx.x & 31;
    const float* xr = h2 + (size_t)n * D_;
    float acc[E_];
    float ssx = 0.f;
    #pragma unroll
    for (int e = 0; e < E_; e++) acc[e] = 0.f;
    for (int d = lane; d < D_; d += 32) {
        const float xv = xr[d];
        ssx += xv * xv;
        const float xw = xv * n2w[d];
        #pragma unroll
        for (int e = 0; e < E_; e++) acc[e] += xw * gw[e * D_ + d];
    }
    #pragma unroll
    for (int o = 16; o > 0; o >>= 1) ssx += __shfl_xor_sync(~0u, ssx, o);
    #pragma unroll
    for (int e = 0; e < E_; e++)
        #pragma unroll
        for (int o = 16; o > 0; o >>= 1) acc[e] += __shfl_xor_sync(~0u, acc[e], o);
    if (lane == 0) {
        const float invr = rsqrtf(ssx / (float)D_ + 1e-8f);
        float l[E_], ss = 0.f;
        #pragma unroll
        for (int e = 0; e < E_; e++) { l[e] = acc[e] * invr + gb[e]; ss += l[e] * l[e]; }
        const float inv = rsqrtf(ss / (float)E_ + 1.1920929e-7f);
        float m = -INFINITY;
        #pragma unroll
        for (int e = 0; e < E_; e++) { l[e] = l[e] * inv * grw[e] * 2.0f; m = fmaxf(m, l[e]); }
        float sum = 0.f, mx = 0.f;
        #pragma unroll
        for (int e = 0; e < E_; e++) {
            const float ex = __expf(l[e] - m);
            sum += ex; mx = fmaxf(mx, ex);
        }
        const float top = mx / sum;
        g[n] = top / (top + 1e-6f);
    }
}

// ===========================================================================
// SwiGLU over h1 [E][NTOK][FF1] -> act [NTOK][E*FF2]  (rounds to tf32)
// ===========================================================================
__global__ void swiglu_k(const float* __restrict__ h1, float* __restrict__ act)
{
    const size_t total = (size_t)NTOK * KMOE2;
    for (size_t idx = (size_t)blockIdx.x * blockDim.x + threadIdx.x; idx < total;
         idx += (size_t)gridDim.x * blockDim.x) {
        const size_t n = idx >> 14;
        const int    c = (int)(idx & 16383);
        const int    e = c >> 11;
        const int    f = c & 2047;
        const float* base = h1 + (size_t)e * NTOK * FF1_ + n * FF1_ + f;
        const float a = base[0];
        const float b = base[FF2_];
        act[idx] = to_tf32(a * b / (1.f + __expf(-b)));
    }
}

// ===========================================================================
// Batched transpose: out[z][c][r] = tf32(in[z][r][c])
// ===========================================================================
__global__ void transpose_k(const float* __restrict__ in, float* __restrict__ out,
                            int ldin, int ldout,
                            int zDiv, long zi1, long zi2, long zo1, long zo2)
{
    __shared__ float t[32][33];
    const int z = blockIdx.z;
    const int zb = z / zDiv, zh = z - zb * zDiv;
    in  += (size_t)zb * zi1 + (size_t)zh * zi2;
    out += (size_t)zb * zo1 + (size_t)zh * zo2;
    const int c0 = blockIdx.x * 32, r0 = blockIdx.y * 32;
    #pragma unroll
    for (int i = 0; i < 4; i++)
        t[threadIdx.y + i * 8][threadIdx.x] =
            in[(size_t)(r0 + threadIdx.y + i * 8) * ldin + c0 + threadIdx.x];
    __syncthreads();
    #pragma unroll
    for (int i = 0; i < 4; i++)
        out[(size_t)(c0 + threadIdx.y + i * 8) * ldout + r0 + threadIdx.x] =
            to_tf32(t[threadIdx.x][threadIdx.y + i * 8]);
}

// ===========================================================================
// Round-copy to tf32
// ===========================================================================
__global__ void roundcpy_k(const float* __restrict__ in, float* __restrict__ out, int n)
{
    for (int i = blockIdx.x * blockDim.x + threadIdx.x; i < n; i += gridDim.x * blockDim.x)
        out[i] = to_tf32(in[i]);
}

// ===========================================================================
// Launch
// ===========================================================================
static inline int smem_bytes(int bn) { return (2 * 128 * 36 + 2 * bn * 36) * 4; }

extern "C" void kernel_launch(void* const* d_in, const int* in_sizes, int n_in,
                              void* d_out, int out_size)
{
    const float* x      = (const float*)d_in[0];
    const float* w_qkv  = (const float*)d_in[1];
    const float* w_out  = (const float*)d_in[2];
    const float* norm1w = (const float*)d_in[3];
    const float* norm2w = (const float*)d_in[4];
    const float* gate_w = (const float*)d_in[5];
    const float* gate_b = (const float*)d_in[6];
    const float* gate_rw= (const float*)d_in[7];
    const float* w1     = (const float*)d_in[8];
    const float* w2     = (const float*)d_in[9];
    float* out = (float*)d_out;

    float *hn1, *wqkvr, *woutr, *qkv, *vt, *scores, *attno, *h2, *hn2, *gate, *w1t, *w2t, *h1, *act;
    cudaGetSymbolAddress((void**)&hn1,    g_hn1);
    cudaGetSymbolAddress((void**)&wqkvr,  g_wqkvr);
    cudaGetSymbolAddress((void**)&woutr,  g_woutr);
    cudaGetSymbolAddress((void**)&qkv,    g_qkv);
    cudaGetSymbolAddress((void**)&vt,     g_vt);
    cudaGetSymbolAddress((void**)&scores, g_scores);
    cudaGetSymbolAddress((void**)&attno,  g_attno);
    cudaGetSymbolAddress((void**)&h2,     g_h2);
    cudaGetSymbolAddress((void**)&hn2,    g_hn2);
    cudaGetSymbolAddress((void**)&gate,   g_gate);
    cudaGetSymbolAddress((void**)&w1t,    g_w1t);
    cudaGetSymbolAddress((void**)&w2t,    g_w2t);
    cudaGetSymbolAddress((void**)&h1,     g_h1);
    cudaGetSymbolAddress((void**)&act,    g_act);

    cudaFuncSetAttribute(mma_gemm<0,128,true >, cudaFuncAttributeMaxDynamicSharedMemorySize, smem_bytes(128));
    cudaFuncSetAttribute(mma_gemm<0,128,false>, cudaFuncAttributeMaxDynamicSharedMemorySize, smem_bytes(128));
    cudaFuncSetAttribute(mma_gemm<0, 64,true >, cudaFuncAttributeMaxDynamicSharedMemorySize, smem_bytes(64));
    cudaFuncSetAttribute(mma_gemm<1,128,false>, cudaFuncAttributeMaxDynamicSharedMemorySize, smem_bytes(128));
    cudaFuncSetAttribute(mma_gemm<2,128,false>, cudaFuncAttributeMaxDynamicSharedMemorySize, smem_bytes(128));

    // --- weight prep (round to tf32-RN; transpose w1/w2 to [N,K]) ---
    roundcpy_k<<<2048, 256>>>(w_qkv, wqkvr, 3 * D_ * D_);
    roundcpy_k<<<1024, 256>>>(w_out, woutr, D_ * D_);
    transpose_k<<<dim3(FF1_ / 32, D_ / 32, E_), dim3(32, 8)>>>(
        w1, w1t, FF1_, D_, 1, (long)D_ * FF1_, 0, (long)D_ * FF1_, 0);
    transpose_k<<<dim3(D_ / 32, KMOE2 / 32, 1), dim3(32, 8)>>>(
        w2, w2t, D_, KMOE2, 1, 0, 0, 0, 0);

    // --- 1) rmsnorm1 ---
    rmsnorm_k<<<NTOK, 256>>>(x, norm1w, hn1, 1e-8f);

    // --- 2) QKV [4096,3072] = hn1 x wqkvr^T ---
    mma_gemm<0,128,true><<<dim3(3 * D_ / 128, NTOK / 128, 1), 256, smem_bytes(128)>>>(
        hn1, wqkvr, qkv, nullptr, nullptr,
        NTOK, 3 * D_, D_, D_, D_, 3 * D_,
        1, 0, 0, 0, 0, 0, 0, 1.f);

    // --- 3) V transpose: vt[b][h][k][n] = qkv[b, n, 2D + h*64 + k] ---
    transpose_k<<<dim3(DH_ / 32, S_ / 32, B_ * H_), dim3(32, 8)>>>(
        qkv + 2 * D_, vt, 3 * D_, S_,
        H_, (long)S_ * 3 * D_, (long)DH_,
        (long)H_ * DH_ * S_, (long)DH_ * S_);

    // --- 4) scores = Q K^T / 8 ---
    mma_gemm<0,128,true><<<dim3(S_ / 128, S_ / 128, B_ * H_), 256, smem_bytes(128)>>>(
        qkv, qkv + D_, scores, nullptr, nullptr,
        S_, S_, DH_, 3 * D_, 3 * D_, S_,
        H_,
        (long)S_ * 3 * D_, (long)DH_,
        (long)S_ * 3 * D_, (long)DH_,
        (long)H_ * S_ * S_, (long)S_ * S_,
        0.125f);

    // --- 5) softmax ---
    softmax_k<<<B_ * H_ * S_, 256>>>(scores);

    // --- 6) O = P V   (N=64 per head; vt rows are headdim, K-major over seq) ---
    mma_gemm<0,64,true><<<dim3(1, S_ / 128, B_ * H_), 256, smem_bytes(64)>>>(
        scores, vt, attno, nullptr, nullptr,
        S_, DH_, S_, S_, S_, D_,
        H_,
        (long)H_ * S_ * S_, (long)S_ * S_,
        (long)H_ * DH_ * S_, (long)DH_ * S_,
        (long)S_ * D_, (long)DH_,
        1.f);

    // --- 7) h2 = x + O w_out^T ---
    mma_gemm<1,128,false><<<dim3(D_ / 128, NTOK / 128, 1), 256, smem_bytes(128)>>>(
        attno, woutr, h2, x, nullptr,
        NTOK, D_, D_, D_, D_, D_,
        1, 0, 0, 0, 0, 0, 0, 1.f);

    // --- 8) rmsnorm2 (for MoE GEMM input) + gate (from raw h2) ---
    rmsnorm_k<<<NTOK, 256>>>(h2, norm2w, hn2, 1e-8f);
    gate_k<<<NTOK / 4, 128>>>(h2, norm2w, gate_w, gate_b, gate_rw, gate);

    // --- 9) MoE1: h1[e] = hn2 x w1t[e]^T   [4096,4096] per expert ---
    mma_gemm<0,128,false><<<dim3(FF1_ / 128, NTOK / 128, E_), 256, smem_bytes(128)>>>(
        hn2, w1t, h1, nullptr, nullptr,
        NTOK, FF1_, D_, D_, D_, FF1_,
        1,
        0, 0,
        (long)FF1_ * D_, 0,
        (long)NTOK * FF1_, 0,
        1.f);

    // --- 10) SwiGLU -> act [4096, 16384] ---
    swiglu_k<<<32768, 256>>>(h1, act);

    // --- 11) MoE2: out = h2 + (act x w2t^T) * g[n] ---
    mma_gemm<2,128,false><<<dim3(D_ / 128, NTOK / 128, 1), 256, smem_bytes(128)>>>(
        act, w2t, out, h2, gate,
        NTOK, D_, KMOE2, KMOE2, KMOE2, D_,
        1, 0, 0, 0, 0, 0, 0, 1.f);

    (void)in_sizes; (void)n_in; (void)out_size;
}

// round 5
// speedup vs baseline: 3.6090x; 1.0544x over previous
#include <cuda_runtime.h>
#include <cstdint>
#include <cmath>

// ===========================================================================
// Problem constants
// ===========================================================================
static constexpr int B_   = 4;
static constexpr int S_   = 1024;
static constexpr int D_   = 1024;
static constexpr int H_   = 16;
static constexpr int DH_  = 64;
static constexpr int E_   = 8;
static constexpr int FF1_ = 4096;
static constexpr int FF2_ = 2048;
static constexpr int NTOK = B_ * S_;        // 4096
static constexpr int KMOE2 = E_ * FF2_;     // 16384

// ===========================================================================
// Scratch
// ===========================================================================
__device__ float g_hn1   [(size_t)NTOK * D_];
__device__ float g_wqkvr [(size_t)3 * D_ * D_];
__device__ float g_woutr [(size_t)D_ * D_];
__device__ float g_qkv   [(size_t)NTOK * 3 * D_];
__device__ float g_vt    [(size_t)B_ * H_ * DH_ * S_];
__device__ float g_scores[(size_t)B_ * H_ * S_ * S_];
__device__ float g_attno [(size_t)NTOK * D_];
__device__ float g_h2    [(size_t)NTOK * D_];
__device__ float g_hn2   [(size_t)NTOK * D_];
__device__ float g_gate  [NTOK];
__device__ float g_w1t   [(size_t)E_ * FF1_ * D_];
__device__ float g_w2t   [(size_t)D_ * KMOE2];
__device__ float g_act   [(size_t)NTOK * KMOE2];

// ===========================================================================
// Helpers
// ===========================================================================
__device__ __forceinline__ uint32_t smem_u32(const void* p) {
    uint32_t a;
    asm("{ .reg .u64 t; cvta.to.shared.u64 t, %1; cvt.u32.u64 %0, t; }" : "=r"(a) : "l"(p));
    return a;
}
__device__ __forceinline__ float to_tf32(float x) {
    uint32_t u;
    asm("cvt.rna.tf32.f32 %0, %1;" : "=r"(u) : "f"(x));
    return __uint_as_float(u);
}

#define CP16(dst, src) \
    asm volatile("cp.async.cg.shared.global [%0], [%1], 16;" :: "r"(dst), "l"(src))
#define CP_COMMIT()  asm volatile("cp.async.commit_group;" ::: "memory")
#define CP_WAIT1()   asm volatile("cp.async.wait_group 1;" ::: "memory")
#define CP_WAIT0()   asm volatile("cp.async.wait_group 0;" ::: "memory")

__device__ __forceinline__ void mma_tf32(float& c0, float& c1, float& c2, float& c3,
                                         uint32_t a0, uint32_t a1, uint32_t a2, uint32_t a3,
                                         uint32_t b0, uint32_t b1)
{
    asm volatile(
        "mma.sync.aligned.m16n8k8.row.col.f32.tf32.tf32.f32 "
        "{%0,%1,%2,%3}, {%4,%5,%6,%7}, {%8,%9}, {%0,%1,%2,%3};"
        : "+f"(c0), "+f"(c1), "+f"(c2), "+f"(c3)
        : "r"(a0), "r"(a1), "r"(a2), "r"(a3), "r"(b0), "r"(b1));
}

// ===========================================================================
// mma.sync tf32 NT GEMM: C[M,N] = alpha * A[M,K](K-major) * B[N,K](K-major)^T
//   EPI 0: C = alpha*acc (optionally tf32-rounded)
//   EPI 1: C = acc + Res
//   EPI 2: C = Res + acc * Gvec[row]
// Tiles: 128 x BN x 32, 8 warps (4m x 2n), warp tile 32 x BN/2.
// ===========================================================================
template<int EPI, int BN, bool ROUND>
__global__ void __launch_bounds__(256)
mma_gemm(const float* __restrict__ A, const float* __restrict__ B,
         float* __restrict__ C, const float* __restrict__ Res,
         const float* __restrict__ Gvec,
         int M, int N, int K, int lda, int ldb, int ldc,
         int zDiv, long sA1, long sA2, long sB1, long sB2, long sC1, long sC2,
         float alpha)
{
    constexpr int NT = BN / 16;
    constexpr int ASTG = 128 * 36;
    constexpr int BSTG = BN * 36;

    extern __shared__ __align__(16) float sm[];
    const uint32_t sbase = smem_u32(sm);
    const int tid = threadIdx.x, wid = tid >> 5, lane = tid & 31;
    const int warp_m = wid & 3, warp_n = wid >> 2;

    const int bz = blockIdx.z;
    const int zb = bz / zDiv, zh = bz - zb * zDiv;
    A += (size_t)zb * sA1 + (size_t)zh * sA2;
    B += (size_t)zb * sB1 + (size_t)zh * sB2;
    const size_t coff = (size_t)zb * sC1 + (size_t)zh * sC2;
    C += coff;
    if (EPI == 1 || EPI == 2) Res += coff;

    const int bm = blockIdx.y * 128;
    const int bn = blockIdx.x * BN;
    A += (size_t)bm * lda;
    B += (size_t)bn * ldb;

    const int nk = K / 32;

    auto loadA = [&](int s, int kt) {
        const float* base = A + kt * 32;
        const uint32_t dbase = sbase + (uint32_t)(s * ASTG) * 4;
        #pragma unroll
        for (int i = 0; i < 4; i++) {
            const int c = tid + i * 256;
            const int row = c >> 3, kc = c & 7;
            CP16(dbase + (uint32_t)row * 144 + (uint32_t)kc * 16,
                 base + (size_t)row * lda + kc * 4);
        }
    };
    auto loadB = [&](int s, int kt) {
        const float* base = B + kt * 32;
        const uint32_t dbase = sbase + (uint32_t)(2 * ASTG + s * BSTG) * 4;
        #pragma unroll
        for (int i = 0; i < BN / 32; i++) {
            const int c = tid + i * 256;
            const int row = c >> 3, kc = c & 7;
            CP16(dbase + (uint32_t)row * 144 + (uint32_t)kc * 16,
                 base + (size_t)row * ldb + kc * 4);
        }
    };

    float acc[2][NT][4];
    #pragma unroll
    for (int mi = 0; mi < 2; mi++)
        #pragma unroll
        for (int ni = 0; ni < NT; ni++)
            #pragma unroll
            for (int j = 0; j < 4; j++) acc[mi][ni][j] = 0.f;

    loadA(0, 0); loadB(0, 0); CP_COMMIT();

    const int lq = lane >> 2;
    const int lr = lane & 3;

    for (int kt = 0; kt < nk; kt++) {
        const int cs = kt & 1;
        if (kt + 1 < nk) {
            loadA(cs ^ 1, kt + 1); loadB(cs ^ 1, kt + 1); CP_COMMIT();
            CP_WAIT1();
        } else {
            CP_WAIT0();
        }
        __syncthreads();

        const float* As = sm + cs * ASTG;
        const float* Bs = sm + 2 * ASTG + cs * BSTG;

        #pragma unroll
        for (int ks = 0; ks < 4; ks++) {
            const int kk = ks * 8 + lr;
            uint32_t a[2][4];
            #pragma unroll
            for (int mi = 0; mi < 2; mi++) {
                const int r0 = warp_m * 32 + mi * 16 + lq;
                a[mi][0] = __float_as_uint(As[r0 * 36 + kk]);
                a[mi][1] = __float_as_uint(As[(r0 + 8) * 36 + kk]);
                a[mi][2] = __float_as_uint(As[r0 * 36 + kk + 4]);
                a[mi][3] = __float_as_uint(As[(r0 + 8) * 36 + kk + 4]);
            }
            uint32_t b[NT][2];
            #pragma unroll
            for (int ni = 0; ni < NT; ni++) {
                const int n0 = warp_n * (BN / 2) + ni * 8 + lq;
                b[ni][0] = __float_as_uint(Bs[n0 * 36 + kk]);
                b[ni][1] = __float_as_uint(Bs[n0 * 36 + kk + 4]);
            }
            #pragma unroll
            for (int mi = 0; mi < 2; mi++)
                #pragma unroll
                for (int ni = 0; ni < NT; ni++)
                    mma_tf32(acc[mi][ni][0], acc[mi][ni][1], acc[mi][ni][2], acc[mi][ni][3],
                             a[mi][0], a[mi][1], a[mi][2], a[mi][3],
                             b[ni][0], b[ni][1]);
        }
        __syncthreads();
    }

    #pragma unroll
    for (int mi = 0; mi < 2; mi++) {
        const int row0 = bm + warp_m * 32 + mi * 16 + lq;
        float gv0 = 1.f, gv1 = 1.f;
        if (EPI == 2) { gv0 = Gvec[row0]; gv1 = Gvec[row0 + 8]; }
        #pragma unroll
        for (int ni = 0; ni < NT; ni++) {
            const int col = bn + warp_n * (BN / 2) + ni * 8 + lr * 2;
            const size_t i0 = (size_t)row0 * ldc + col;
            const size_t i1 = (size_t)(row0 + 8) * ldc + col;
            float2 o0, o1;
            if (EPI == 0) {
                o0.x = alpha * acc[mi][ni][0]; o0.y = alpha * acc[mi][ni][1];
                o1.x = alpha * acc[mi][ni][2]; o1.y = alpha * acc[mi][ni][3];
                if (ROUND) {
                    o0.x = to_tf32(o0.x); o0.y = to_tf32(o0.y);
                    o1.x = to_tf32(o1.x); o1.y = to_tf32(o1.y);
                }
            } else if (EPI == 1) {
                float2 r0 = *(const float2*)&Res[i0];
                float2 r1 = *(const float2*)&Res[i1];
                o0.x = acc[mi][ni][0] + r0.x; o0.y = acc[mi][ni][1] + r0.y;
                o1.x = acc[mi][ni][2] + r1.x; o1.y = acc[mi][ni][3] + r1.y;
            } else {
                float2 r0 = *(const float2*)&Res[i0];
                float2 r1 = *(const float2*)&Res[i1];
                o0.x = r0.x + acc[mi][ni][0] * gv0; o0.y = r0.y + acc[mi][ni][1] * gv0;
                o1.x = r1.x + acc[mi][ni][2] * gv1; o1.y = r1.y + acc[mi][ni][3] * gv1;
            }
            *(float2*)&C[i0] = o0;
            *(float2*)&C[i1] = o1;
        }
    }
}

// ===========================================================================
// Fused MoE1 + SwiGLU:
//   act[n, e*FF2 + f] = tf32( (hn2 @ w1t[e,f,:]) * silu(hn2 @ w1t[e,f+2048,:]) )
// CTA: 128 tokens x 64 act-cols; B tile holds BOTH halves, interleaved by
// 8-row groups (even group = a-half, odd group = b-half, same local cols) so
// every warp's even n-tiles are 'a' and odd n-tiles are 'b' at matching
// lanes. Mainloop identical to mma_gemm<BN=128>.
// Grid: (FF2/64, NTOK/128, E)
// ===========================================================================
__global__ void __launch_bounds__(256)
moe1_swiglu(const float* __restrict__ hn2, const float* __restrict__ w1t,
            float* __restrict__ act)
{
    constexpr int BN = 128;
    constexpr int NT = 8;
    constexpr int ASTG = 128 * 36;
    constexpr int BSTG = BN * 36;

    extern __shared__ __align__(16) float sm[];
    const uint32_t sbase = smem_u32(sm);
    const int tid = threadIdx.x, wid = tid >> 5, lane = tid & 31;
    const int warp_m = wid & 3, warp_n = wid >> 2;

    const int e    = blockIdx.z;
    const int bn_a = blockIdx.x * 64;       // act column base within expert
    const int bm   = blockIdx.y * 128;

    const float* A = hn2 + (size_t)bm * D_;
    const float* Be = w1t + (size_t)e * FF1_ * D_;

    const int nk = D_ / 32;                  // 32

    auto loadA = [&](int s, int kt) {
        const float* base = A + kt * 32;
        const uint32_t dbase = sbase + (uint32_t)(s * ASTG) * 4;
        #pragma unroll
        for (int i = 0; i < 4; i++) {
            const int c = tid + i * 256;
            const int row = c >> 3, kc = c & 7;
            CP16(dbase + (uint32_t)row * 144 + (uint32_t)kc * 16,
                 base + (size_t)row * D_ + kc * 4);
        }
    };
    // B row r -> w1t row: half=(r>>3)&1, col=((r>>4)<<3)+(r&7)
    auto loadB = [&](int s, int kt) {
        const uint32_t dbase = sbase + (uint32_t)(2 * ASTG + s * BSTG) * 4;
        #pragma unroll
        for (int i = 0; i < 4; i++) {
            const int c = tid + i * 256;
            const int row = c >> 3, kc = c & 7;
            const int half = (row >> 3) & 1;
            const int coll = ((row >> 4) << 3) + (row & 7);
            const int wrow = bn_a + coll + half * FF2_;
            CP16(dbase + (uint32_t)row * 144 + (uint32_t)kc * 16,
                 Be + (size_t)wrow * D_ + kt * 32 + kc * 4);
        }
    };

    float acc[2][NT][4];
    #pragma unroll
    for (int mi = 0; mi < 2; mi++)
        #pragma unroll
        for (int ni = 0; ni < NT; ni++)
            #pragma unroll
            for (int j = 0; j < 4; j++) acc[mi][ni][j] = 0.f;

    loadA(0, 0); loadB(0, 0); CP_COMMIT();

    const int lq = lane >> 2;
    const int lr = lane & 3;

    for (int kt = 0; kt < nk; kt++) {
        const int cs = kt & 1;
        if (kt + 1 < nk) {
            loadA(cs ^ 1, kt + 1); loadB(cs ^ 1, kt + 1); CP_COMMIT();
            CP_WAIT1();
        } else {
            CP_WAIT0();
        }
        __syncthreads();

        const float* As = sm + cs * ASTG;
        const float* Bs = sm + 2 * ASTG + cs * BSTG;

        #pragma unroll
        for (int ks = 0; ks < 4; ks++) {
            const int kk = ks * 8 + lr;
            uint32_t a[2][4];
            #pragma unroll
            for (int mi = 0; mi < 2; mi++) {
                const int r0 = warp_m * 32 + mi * 16 + lq;
                a[mi][0] = __float_as_uint(As[r0 * 36 + kk]);
                a[mi][1] = __float_as_uint(As[(r0 + 8) * 36 + kk]);
                a[mi][2] = __float_as_uint(As[r0 * 36 + kk + 4]);
                a[mi][3] = __float_as_uint(As[(r0 + 8) * 36 + kk + 4]);
            }
            uint32_t b[NT][2];
            #pragma unroll
            for (int ni = 0; ni < NT; ni++) {
                const int n0 = warp_n * 64 + ni * 8 + lq;
                b[ni][0] = __float_as_uint(Bs[n0 * 36 + kk]);
                b[ni][1] = __float_as_uint(Bs[n0 * 36 + kk + 4]);
            }
            #pragma unroll
            for (int mi = 0; mi < 2; mi++)
                #pragma unroll
                for (int ni = 0; ni < NT; ni++)
                    mma_tf32(acc[mi][ni][0], acc[mi][ni][1], acc[mi][ni][2], acc[mi][ni][3],
                             a[mi][0], a[mi][1], a[mi][2], a[mi][3],
                             b[ni][0], b[ni][1]);
        }
        __syncthreads();
    }

    // ---- epilogue: act = tf32(a * silu(b)), even/odd n-tile pairs
    #pragma unroll
    for (int mi = 0; mi < 2; mi++) {
        const int row0 = bm + warp_m * 32 + mi * 16 + lq;
        #pragma unroll
        for (int p = 0; p < 4; p++) {
            const float* av = acc[mi][2 * p];
            const float* bv = acc[mi][2 * p + 1];
            float2 o0, o1;
            o0.x = to_tf32(av[0] * bv[0] / (1.f + __expf(-bv[0])));
            o0.y = to_tf32(av[1] * bv[1] / (1.f + __expf(-bv[1])));
            o1.x = to_tf32(av[2] * bv[2] / (1.f + __expf(-bv[2])));
            o1.y = to_tf32(av[3] * bv[3] / (1.f + __expf(-bv[3])));
            const int col = e * FF2_ + bn_a + warp_n * 32 + p * 8 + lr * 2;
            *(float2*)&act[(size_t)row0 * KMOE2 + col] = o0;
            *(float2*)&act[(size_t)(row0 + 8) * KMOE2 + col] = o1;
        }
    }
}

// ===========================================================================
// RMSNorm (rounds output to tf32)
// ===========================================================================
__global__ void rmsnorm_k(const float* __restrict__ x, const float* __restrict__ w,
                          float* __restrict__ y, float eps)
{
    const int row = blockIdx.x;
    const float* xr = x + (size_t)row * D_;
    float v[4];
    float s = 0.f;
    #pragma unroll
    for (int i = 0; i < 4; i++) { v[i] = xr[threadIdx.x + 256 * i]; s += v[i] * v[i]; }
    #pragma unroll
    for (int o = 16; o > 0; o >>= 1) s += __shfl_xor_sync(~0u, s, o);
    __shared__ float red[8];
    if ((threadIdx.x & 31) == 0) red[threadIdx.x >> 5] = s;
    __syncthreads();
    if (threadIdx.x < 8) {
        float t = red[threadIdx.x];
        #pragma unroll
        for (int o = 4; o > 0; o >>= 1) t += __shfl_xor_sync(0xffu, t, o);
        if (threadIdx.x == 0) red[0] = t;
    }
    __syncthreads();
    const float inv = rsqrtf(red[0] / (float)D_ + eps);
    float* yr = y + (size_t)row * D_;
    #pragma unroll
    for (int i = 0; i < 4; i++)
        yr[threadIdx.x + 256 * i] = to_tf32(v[i] * inv * w[threadIdx.x + 256 * i]);
}

// ===========================================================================
// Softmax over 1024-length rows, register-resident, rounds output to tf32
// ===========================================================================
__global__ void softmax_k(float* __restrict__ sc)
{
    float* p = sc + (size_t)blockIdx.x * S_;
    const int t = threadIdx.x;
    float v[4];
    #pragma unroll
    for (int i = 0; i < 4; i++) v[i] = p[t + 256 * i];
    float m = fmaxf(fmaxf(v[0], v[1]), fmaxf(v[2], v[3]));
    #pragma unroll
    for (int o = 16; o > 0; o >>= 1) m = fmaxf(m, __shfl_xor_sync(~0u, m, o));
    __shared__ float red[8];
    if ((t & 31) == 0) red[t >> 5] = m;
    __syncthreads();
    float mm = fmaxf(fmaxf(red[0], red[1]), fmaxf(red[2], red[3]));
    mm = fmaxf(mm, fmaxf(fmaxf(red[4], red[5]), fmaxf(red[6], red[7])));
    float s = 0.f;
    #pragma unroll
    for (int i = 0; i < 4; i++) { v[i] = __expf(v[i] - mm); s += v[i]; }
    #pragma unroll
    for (int o = 16; o > 0; o >>= 1) s += __shfl_xor_sync(~0u, s, o);
    __syncthreads();
    if ((t & 31) == 0) red[t >> 5] = s;
    __syncthreads();
    float ss = red[0] + red[1] + red[2] + red[3] + red[4] + red[5] + red[6] + red[7];
    const float inv = 1.f / ss;
    #pragma unroll
    for (int i = 0; i < 4; i++) p[t + 256 * i] = to_tf32(v[i] * inv);
}

// ===========================================================================
// Gating — from raw fp32 h2 (exact path)
// ===========================================================================
__global__ void gate_k(const float* __restrict__ h2, const float* __restrict__ n2w,
                       const float* __restrict__ gw,
                       const float* __restrict__ gb, const float* __restrict__ grw,
                       float* __restrict__ g)
{
    const int n    = blockIdx.x * 4 + (threadIdx.x >> 5);
    const int lane = threadIdx.x & 31;
    const float* xr = h2 + (size_t)n * D_;
    float acc[E_];
    float ssx = 0.f;
    #pragma unroll
    for (int e = 0; e < E_; e++) acc[e] = 0.f;
    for (int d = lane; d < D_; d += 32) {
        const float xv = xr[d];
        ssx += xv * xv;
        const float xw = xv * n2w[d];
        #pragma unroll
        for (int e = 0; e < E_; e++) acc[e] += xw * gw[e * D_ + d];
    }
    #pragma unroll
    for (int o = 16; o > 0; o >>= 1) ssx += __shfl_xor_sync(~0u, ssx, o);
    #pragma unroll
    for (int e = 0; e < E_; e++)
        #pragma unroll
        for (int o = 16; o > 0; o >>= 1) acc[e] += __shfl_xor_sync(~0u, acc[e], o);
    if (lane == 0) {
        const float invr = rsqrtf(ssx / (float)D_ + 1e-8f);
        float l[E_], ss = 0.f;
        #pragma unroll
        for (int e = 0; e < E_; e++) { l[e] = acc[e] * invr + gb[e]; ss += l[e] * l[e]; }
        const float inv = rsqrtf(ss / (float)E_ + 1.1920929e-7f);
        float m = -INFINITY;
        #pragma unroll
        for (int e = 0; e < E_; e++) { l[e] = l[e] * inv * grw[e] * 2.0f; m = fmaxf(m, l[e]); }
        float sum = 0.f, mx = 0.f;
        #pragma unroll
        for (int e = 0; e < E_; e++) {
            const float ex = __expf(l[e] - m);
            sum += ex; mx = fmaxf(mx, ex);
        }
        const float top = mx / sum;
        g[n] = top / (top + 1e-6f);
    }
}

// ===========================================================================
// Batched transpose: out[z][c][r] = tf32(in[z][r][c])
// ===========================================================================
__global__ void transpose_k(const float* __restrict__ in, float* __restrict__ out,
                            int ldin, int ldout,
                            int zDiv, long zi1, long zi2, long zo1, long zo2)
{
    __shared__ float t[32][33];
    const int z = blockIdx.z;
    const int zb = z / zDiv, zh = z - zb * zDiv;
    in  += (size_t)zb * zi1 + (size_t)zh * zi2;
    out += (size_t)zb * zo1 + (size_t)zh * zo2;
    const int c0 = blockIdx.x * 32, r0 = blockIdx.y * 32;
    #pragma unroll
    for (int i = 0; i < 4; i++)
        t[threadIdx.y + i * 8][threadIdx.x] =
            in[(size_t)(r0 + threadIdx.y + i * 8) * ldin + c0 + threadIdx.x];
    __syncthreads();
    #pragma unroll
    for (int i = 0; i < 4; i++)
        out[(size_t)(c0 + threadIdx.y + i * 8) * ldout + r0 + threadIdx.x] =
            to_tf32(t[threadIdx.x][threadIdx.y + i * 8]);
}

// ===========================================================================
// Round-copy to tf32
// ===========================================================================
__global__ void roundcpy_k(const float* __restrict__ in, float* __restrict__ out, int n)
{
    for (int i = blockIdx.x * blockDim.x + threadIdx.x; i < n; i += gridDim.x * blockDim.x)
        out[i] = to_tf32(in[i]);
}

// ===========================================================================
// Launch
// ===========================================================================
static inline int smem_bytes(int bn) { return (2 * 128 * 36 + 2 * bn * 36) * 4; }

extern "C" void kernel_launch(void* const* d_in, const int* in_sizes, int n_in,
                              void* d_out, int out_size)
{
    const float* x      = (const float*)d_in[0];
    const float* w_qkv  = (const float*)d_in[1];
    const float* w_out  = (const float*)d_in[2];
    const float* norm1w = (const float*)d_in[3];
    const float* norm2w = (const float*)d_in[4];
    const float* gate_w = (const float*)d_in[5];
    const float* gate_b = (const float*)d_in[6];
    const float* gate_rw= (const float*)d_in[7];
    const float* w1     = (const float*)d_in[8];
    const float* w2     = (const float*)d_in[9];
    float* out = (float*)d_out;

    float *hn1, *wqkvr, *woutr, *qkv, *vt, *scores, *attno, *h2, *hn2, *gate, *w1t, *w2t, *act;
    cudaGetSymbolAddress((void**)&hn1,    g_hn1);
    cudaGetSymbolAddress((void**)&wqkvr,  g_wqkvr);
    cudaGetSymbolAddress((void**)&woutr,  g_woutr);
    cudaGetSymbolAddress((void**)&qkv,    g_qkv);
    cudaGetSymbolAddress((void**)&vt,     g_vt);
    cudaGetSymbolAddress((void**)&scores, g_scores);
    cudaGetSymbolAddress((void**)&attno,  g_attno);
    cudaGetSymbolAddress((void**)&h2,     g_h2);
    cudaGetSymbolAddress((void**)&hn2,    g_hn2);
    cudaGetSymbolAddress((void**)&gate,   g_gate);
    cudaGetSymbolAddress((void**)&w1t,    g_w1t);
    cudaGetSymbolAddress((void**)&w2t,    g_w2t);
    cudaGetSymbolAddress((void**)&act,    g_act);

    cudaFuncSetAttribute(mma_gemm<0,128,true >, cudaFuncAttributeMaxDynamicSharedMemorySize, smem_bytes(128));
    cudaFuncSetAttribute(mma_gemm<0, 64,true >, cudaFuncAttributeMaxDynamicSharedMemorySize, smem_bytes(64));
    cudaFuncSetAttribute(mma_gemm<1,128,false>, cudaFuncAttributeMaxDynamicSharedMemorySize, smem_bytes(128));
    cudaFuncSetAttribute(mma_gemm<2,128,false>, cudaFuncAttributeMaxDynamicSharedMemorySize, smem_bytes(128));
    cudaFuncSetAttribute(moe1_swiglu,          cudaFuncAttributeMaxDynamicSharedMemorySize, smem_bytes(128));

    // --- weight prep ---
    roundcpy_k<<<2048, 256>>>(w_qkv, wqkvr, 3 * D_ * D_);
    roundcpy_k<<<1024, 256>>>(w_out, woutr, D_ * D_);
    transpose_k<<<dim3(FF1_ / 32, D_ / 32, E_), dim3(32, 8)>>>(
        w1, w1t, FF1_, D_, 1, (long)D_ * FF1_, 0, (long)D_ * FF1_, 0);
    transpose_k<<<dim3(D_ / 32, KMOE2 / 32, 1), dim3(32, 8)>>>(
        w2, w2t, D_, KMOE2, 1, 0, 0, 0, 0);

    // --- 1) rmsnorm1 ---
    rmsnorm_k<<<NTOK, 256>>>(x, norm1w, hn1, 1e-8f);

    // --- 2) QKV ---
    mma_gemm<0,128,true><<<dim3(3 * D_ / 128, NTOK / 128, 1), 256, smem_bytes(128)>>>(
        hn1, wqkvr, qkv, nullptr, nullptr,
        NTOK, 3 * D_, D_, D_, D_, 3 * D_,
        1, 0, 0, 0, 0, 0, 0, 1.f);

    // --- 3) V transpose ---
    transpose_k<<<dim3(DH_ / 32, S_ / 32, B_ * H_), dim3(32, 8)>>>(
        qkv + 2 * D_, vt, 3 * D_, S_,
        H_, (long)S_ * 3 * D_, (long)DH_,
        (long)H_ * DH_ * S_, (long)DH_ * S_);

    // --- 4) scores = Q K^T / 8 ---
    mma_gemm<0,128,true><<<dim3(S_ / 128, S_ / 128, B_ * H_), 256, smem_bytes(128)>>>(
        qkv, qkv + D_, scores, nullptr, nullptr,
        S_, S_, DH_, 3 * D_, 3 * D_, S_,
        H_,
        (long)S_ * 3 * D_, (long)DH_,
        (long)S_ * 3 * D_, (long)DH_,
        (long)H_ * S_ * S_, (long)S_ * S_,
        0.125f);

    // --- 5) softmax ---
    softmax_k<<<B_ * H_ * S_, 256>>>(scores);

    // --- 6) O = P V ---
    mma_gemm<0,64,true><<<dim3(1, S_ / 128, B_ * H_), 256, smem_bytes(64)>>>(
        scores, vt, attno, nullptr, nullptr,
        S_, DH_, S_, S_, S_, D_,
        H_,
        (long)H_ * S_ * S_, (long)S_ * S_,
        (long)H_ * DH_ * S_, (long)DH_ * S_,
        (long)S_ * D_, (long)DH_,
        1.f);

    // --- 7) h2 = x + O w_out^T ---
    mma_gemm<1,128,false><<<dim3(D_ / 128, NTOK / 128, 1), 256, smem_bytes(128)>>>(
        attno, woutr, h2, x, nullptr,
        NTOK, D_, D_, D_, D_, D_,
        1, 0, 0, 0, 0, 0, 0, 1.f);

    // --- 8) rmsnorm2 + gate ---
    rmsnorm_k<<<NTOK, 256>>>(h2, norm2w, hn2, 1e-8f);
    gate_k<<<NTOK / 4, 128>>>(h2, norm2w, gate_w, gate_b, gate_rw, gate);

    // --- 9+10) fused MoE1 + SwiGLU -> act [4096, 16384] ---
    moe1_swiglu<<<dim3(FF2_ / 64, NTOK / 128, E_), 256, smem_bytes(128)>>>(
        hn2, w1t, act);

    // --- 11) MoE2: out = h2 + (act x w2t^T) * g[n] ---
    mma_gemm<2,128,false><<<dim3(D_ / 128, NTOK / 128, 1), 256, smem_bytes(128)>>>(
        act, w2t, out, h2, gate,
        NTOK, D_, KMOE2, KMOE2, KMOE2, D_,
        1, 0, 0, 0, 0, 0, 0, 1.f);

    (void)in_sizes; (void)n_in; (void)out_size;
}